// round 4
// baseline (speedup 1.0000x reference)
#include <cuda_runtime.h>

#define LSEQ 64
#define HDIM 128
#define KTOT 1024        // W is [1024, 128]; contraction runs over all 1024 rows
#define NKC  16          // k-chunks of 64
#define APITCH 68        // AcT pitch (float4-aligned)
#define SPITCH 65        // scores pitch (scalar access)

// Precomputed bilinear form and bias cross-terms (scaled by 1/1024)
struct Pre {
    float M[HDIM * HDIM];
    float u[HDIM];
    float v[HDIM];
    float s0;
};
__device__ Pre g_pre;

// Split-k partial buffers (each element written by exactly one thread per replay)
__device__ float g_partial[NKC][HDIM * HDIM];
__device__ float g_pu[NKC][HDIM];
__device__ float g_pv[NKC][HDIM];
__device__ float g_ps0[NKC];

// ---------------------------------------------------------------------------
// K1: partial[kc][e][d] = sum_{o in chunk kc} Wp[o][e] * Wc[o][d]
// grid 128 = 8 row-tiles (16 e each) x 16 k-chunks (64 each). 256 threads.
// ---------------------------------------------------------------------------
__global__ void __launch_bounds__(256)
pre_slab(const float* __restrict__ Wp, const float* __restrict__ Wc,
         const float* __restrict__ bp, const float* __restrict__ bc) {
    __shared__ float wp[64][16];          // wp[k][e] for this (rowtile, kchunk)
    __shared__ float s0red[64];
    const int t  = threadIdx.x;
    const int rt = blockIdx.x >> 4;       // 0..7
    const int kc = blockIdx.x & 15;       // 0..15
    const int e0 = rt * 16;
    const int K0 = kc * 64;

    for (int i = t; i < 64 * 16; i += 256) {
        int k = i >> 4, e = i & 15;
        wp[k][e] = Wp[(size_t)(K0 + k) * HDIM + e0 + e];
    }
    __syncthreads();

    const int w = t >> 5, l = t & 31;
    const int ea = 2 * w;                 // 2 e-rows per warp (8 warps x 2 = 16)
    const int d0 = 4 * l;
    float4 acc0 = {0, 0, 0, 0}, acc1 = {0, 0, 0, 0};
    const float* WcB = Wc + (size_t)K0 * HDIM + d0;

    #pragma unroll 8
    for (int k = 0; k < 64; k++) {
        float4 b = *(const float4*)(WcB + (size_t)k * HDIM);
        float a0 = wp[k][ea], a1 = wp[k][ea + 1];
        acc0.x += a0 * b.x; acc0.y += a0 * b.y; acc0.z += a0 * b.z; acc0.w += a0 * b.w;
        acc1.x += a1 * b.x; acc1.y += a1 * b.y; acc1.z += a1 * b.z; acc1.w += a1 * b.w;
    }
    float* dst = &g_partial[kc][(size_t)(e0 + ea) * HDIM + d0];
    *(float4*)dst = acc0;
    *(float4*)(dst + HDIM) = acc1;

    // bias partials (zero-valued in this dataset; kept for generality)
    if (rt == 0 && t < HDIM) {
        float s = 0.f;
        for (int k = 0; k < 64; k++) s += Wp[(size_t)(K0 + k) * HDIM + t] * bc[K0 + k];
        g_pu[kc][t] = s;
    } else if (rt == 1 && t < HDIM) {
        float s = 0.f;
        for (int k = 0; k < 64; k++) s += Wc[(size_t)(K0 + k) * HDIM + t] * bp[K0 + k];
        g_pv[kc][t] = s;
    } else if (rt == 2) {
        if (t < 64) s0red[t] = bp[K0 + t] * bc[K0 + t];
        __syncthreads();
        if (t == 0) {
            float s = 0.f;
            for (int i = 0; i < 64; i++) s += s0red[i];
            g_ps0[kc] = s;
        }
    }
}

// ---------------------------------------------------------------------------
// K2: reduce the 16 partials -> g_pre (coalesced, deterministic)
// grid 65 x 256: blocks 0..63 reduce M; block 64 reduces u, v, s0.
// ---------------------------------------------------------------------------
__global__ void __launch_bounds__(256)
pre_reduce() {
    const int t = threadIdx.x, bx = blockIdx.x;
    const float inv = 1.0f / 1024.0f;
    if (bx < 64) {
        int idx = bx * 256 + t;
        float s = 0.f;
        #pragma unroll
        for (int kc = 0; kc < NKC; kc++) s += g_partial[kc][idx];
        g_pre.M[idx] = s * inv;
    } else {
        if (t < HDIM) {
            float s = 0.f;
            #pragma unroll
            for (int kc = 0; kc < NKC; kc++) s += g_pu[kc][t];
            g_pre.u[t] = s * inv;
        } else {
            int e = t - HDIM;
            float s = 0.f;
            #pragma unroll
            for (int kc = 0; kc < NKC; kc++) s += g_pv[kc][e];
            g_pre.v[e] = s * inv;
        }
        if (t == 0) {
            float s = 0.f;
            #pragma unroll
            for (int kc = 0; kc < NKC; kc++) s += g_ps0[kc];
            g_pre.s0 = s * inv;
        }
    }
}

// ---------------------------------------------------------------------------
// Main fused kernel — one CTA per batch element, 512 threads
// ---------------------------------------------------------------------------
struct SmemMain {
    float Ap[LSEQ][HDIM];      // peptide [p][e]       (broadcast reads: pitch 128 ok)
    float Msh[HDIM][HDIM];     // M [e][d]
    float PM[LSEQ][HDIM];      // pep @ M  [p][d]
    float AcT[HDIM][APITCH];   // cdr3 transposed [d][c]
    float S[LSEQ][SPITCH];     // scores -> exp(scores - max)
    float pu[LSEQ], cv[LSEQ], RS[LSEQ], CS[LSEQ];
    float red[16];
    float outP[HDIM], outC[HDIM];
    float mx, Z, s0;
};

__global__ void __launch_bounds__(512, 1)
main_kernel(const float* __restrict__ pep, const float* __restrict__ cdr3,
            float* __restrict__ out) {
    extern __shared__ char smem_raw[];
    SmemMain& sm = *(SmemMain*)smem_raw;
    const int t = threadIdx.x;
    const int b = blockIdx.x;
    const int w = t >> 5, l = t & 31;

    // ---- cooperative loads ----
    const float4* pep4 = (const float4*)(pep + (size_t)b * LSEQ * HDIM);
    const float4* cdr4 = (const float4*)(cdr3 + (size_t)b * LSEQ * HDIM);
    const float4* M4   = (const float4*)g_pre.M;

    float4* Ap4  = (float4*)sm.Ap;    // contiguous pitch-128 copies
    float4* Msh4 = (float4*)sm.Msh;
    for (int i = t; i < LSEQ * (HDIM / 4); i += 512) Ap4[i] = pep4[i];
    for (int i = t; i < HDIM * (HDIM / 4); i += 512) Msh4[i] = M4[i];
    for (int i = t; i < LSEQ * (HDIM / 4); i += 512) {       // cdr3 -> transposed
        int c = i >> 5, d4 = i & 31;
        float4 v = cdr4[i];
        sm.AcT[d4 * 4 + 0][c] = v.x;
        sm.AcT[d4 * 4 + 1][c] = v.y;
        sm.AcT[d4 * 4 + 2][c] = v.z;
        sm.AcT[d4 * 4 + 3][c] = v.w;
    }
    if (t == 0) sm.s0 = g_pre.s0;
    __syncthreads();

    // ---- bias projections (zero in this dataset, kept for generality) ----
    if (t < LSEQ) {
        float s = 0.f;
        for (int e = 0; e < HDIM; e++) s += sm.Ap[t][e] * g_pre.u[e];
        sm.pu[t] = s;
    } else if (t < 2 * LSEQ) {
        int c = t - LSEQ;
        float s = 0.f;
        for (int d = 0; d < HDIM; d++) s += sm.AcT[d][c] * g_pre.v[d];
        sm.cv[c] = s;
    }

    // ---- GEMM1: PM[p][d] = sum_e Ap[p][e] * Msh[e][d] ----
    // 16 warps: warp w -> p in [4w,4w+4), lane l -> d in [4l,4l+4)
    {
        const int p0 = w * 4, d0 = l * 4;
        float acc[4][4];
        #pragma unroll
        for (int i = 0; i < 4; i++)
            #pragma unroll
            for (int j = 0; j < 4; j++) acc[i][j] = 0.f;

        #pragma unroll 4
        for (int e = 0; e < HDIM; e += 4) {
            float4 mv[4];
            #pragma unroll
            for (int q = 0; q < 4; q++) mv[q] = *(const float4*)&sm.Msh[e + q][d0];
            #pragma unroll
            for (int i = 0; i < 4; i++) {
                float4 a = *(const float4*)&sm.Ap[p0 + i][e];   // broadcast
                acc[i][0] += a.x * mv[0].x + a.y * mv[1].x + a.z * mv[2].x + a.w * mv[3].x;
                acc[i][1] += a.x * mv[0].y + a.y * mv[1].y + a.z * mv[2].y + a.w * mv[3].y;
                acc[i][2] += a.x * mv[0].z + a.y * mv[1].z + a.z * mv[2].z + a.w * mv[3].z;
                acc[i][3] += a.x * mv[0].w + a.y * mv[1].w + a.z * mv[2].w + a.w * mv[3].w;
            }
        }
        #pragma unroll
        for (int i = 0; i < 4; i++)
            *(float4*)&sm.PM[p0 + i][d0] =
                make_float4(acc[i][0], acc[i][1], acc[i][2], acc[i][3]);
    }
    __syncthreads();

    // ---- GEMM2: S[p][c] = sum_d PM[p][d]*AcT[d][c] + pu[p] + cv[c] + s0 ----
    // warp w -> p in [4w,4w+4); lane: half = l>>4 covers d-range [64*half,+64),
    // c-tile c0 = (l&15)*4; cross-half reduced via shfl_xor(16).
    {
        const int p0 = w * 4;
        const int db = (l >> 4) * 64;
        const int c0 = (l & 15) * 4;
        float acc[4][4];
        #pragma unroll
        for (int i = 0; i < 4; i++)
            #pragma unroll
            for (int j = 0; j < 4; j++) acc[i][j] = 0.f;

        #pragma unroll 4
        for (int dd = 0; dd < 64; dd += 4) {
            const int d = db + dd;
            float4 av[4];
            #pragma unroll
            for (int q = 0; q < 4; q++) av[q] = *(const float4*)&sm.AcT[d + q][c0];
            #pragma unroll
            for (int i = 0; i < 4; i++) {
                float4 pm = *(const float4*)&sm.PM[p0 + i][d];
                acc[i][0] += pm.x * av[0].x + pm.y * av[1].x + pm.z * av[2].x + pm.w * av[3].x;
                acc[i][1] += pm.x * av[0].y + pm.y * av[1].y + pm.z * av[2].y + pm.w * av[3].y;
                acc[i][2] += pm.x * av[0].z + pm.y * av[1].z + pm.z * av[2].z + pm.w * av[3].z;
                acc[i][3] += pm.x * av[0].w + pm.y * av[1].w + pm.z * av[2].w + pm.w * av[3].w;
            }
        }
        #pragma unroll
        for (int i = 0; i < 4; i++)
            #pragma unroll
            for (int j = 0; j < 4; j++)
                acc[i][j] += __shfl_xor_sync(0xffffffffu, acc[i][j], 16);

        if (l < 16) {
            const float s0v = sm.s0;
            #pragma unroll
            for (int i = 0; i < 4; i++) {
                const float bias = sm.pu[p0 + i] + s0v;
                #pragma unroll
                for (int j = 0; j < 4; j++)
                    sm.S[p0 + i][c0 + j] = acc[i][j] + bias + sm.cv[c0 + j];
            }
        }
    }
    __syncthreads();

    // ---- softmax over all 4096 scores: max ----
    float m = -1e30f;
    #pragma unroll
    for (int q = 0; q < 8; q++) {
        int f = t * 8 + q;
        m = fmaxf(m, sm.S[f >> 6][f & 63]);
    }
    #pragma unroll
    for (int o = 16; o > 0; o >>= 1) m = fmaxf(m, __shfl_xor_sync(~0u, m, o));
    if (l == 0) sm.red[w] = m;
    __syncthreads();
    if (t == 0) {
        float mm = sm.red[0];
        #pragma unroll
        for (int i = 1; i < 16; i++) mm = fmaxf(mm, sm.red[i]);
        sm.mx = mm;
    }
    __syncthreads();

    // ---- exp in place ----
    const float mx = sm.mx;
    #pragma unroll
    for (int q = 0; q < 8; q++) {
        int f = t * 8 + q;
        float* sp = &sm.S[f >> 6][f & 63];
        *sp = __expf(*sp - mx);
    }
    __syncthreads();

    // ---- row sums (RS, weight cdr3) and column sums (CS, weight peptide) ----
    if (t < LSEQ) {
        float s = 0.f;
        for (int c = 0; c < LSEQ; c++) s += sm.S[t][c];
        sm.RS[t] = s;
    } else if (t < 2 * LSEQ) {
        int c = t - LSEQ;
        float s = 0.f;
        for (int p = 0; p < LSEQ; p++) s += sm.S[p][c];
        sm.CS[c] = s;
    }
    __syncthreads();
    if (t < 32) {
        float z = sm.RS[t] + sm.RS[t + 32];
        #pragma unroll
        for (int o = 16; o > 0; o >>= 1) z += __shfl_xor_sync(~0u, z, o);
        if (t == 0) sm.Z = z;
    }
    __syncthreads();

    // ---- epilogue: out[b,h] = (sum_j pep[j][h]*CS[j] + sum_i cdr3[i][h]*RS[i]) / Z
    if (t < HDIM) {
        const int h = t;
        float s = 0.f;
        for (int j = 0; j < LSEQ; j++) s += sm.Ap[j][h] * sm.CS[j];
        sm.outP[h] = s;
    } else if (t < 2 * HDIM) {
        const int h = t - HDIM;
        float s = 0.f;
        for (int i = 0; i < LSEQ; i++) s += sm.AcT[h][i] * sm.RS[i];
        sm.outC[h] = s;
    }
    __syncthreads();
    if (t < HDIM) {
        const float invZ = 1.0f / sm.Z;
        out[(size_t)b * HDIM + t] = (sm.outP[t] + sm.outC[t]) * invZ;
    }
}

// ---------------------------------------------------------------------------
extern "C" void kernel_launch(void* const* d_in, const int* in_sizes, int n_in,
                              void* d_out, int out_size) {
    const float* pep = (const float*)d_in[0];
    const float* cdr = (const float*)d_in[1];
    const float* Wc  = (const float*)d_in[2];
    const float* bc  = (const float*)d_in[3];
    const float* Wp  = (const float*)d_in[4];
    const float* bp  = (const float*)d_in[5];
    float* out = (float*)d_out;

    const int B = in_sizes[0] / (LSEQ * HDIM);   // 256

    cudaFuncSetAttribute(main_kernel, cudaFuncAttributeMaxDynamicSharedMemorySize,
                         (int)sizeof(SmemMain));

    pre_slab<<<128, 256>>>(Wp, Wc, bp, bc);
    pre_reduce<<<65, 256>>>();
    main_kernel<<<B, 512, sizeof(SmemMain)>>>(pep, cdr, out);
}

// round 5
// speedup vs baseline: 1.1312x; 1.1312x over previous
#include <cuda_runtime.h>

#define LSEQ 64
#define HDIM 128
#define KTOT 1024        // W is [1024, 128]; contraction runs over all 1024 rows
#define NKC  32          // k-chunks
#define KC   32          // k per chunk
#define APITCH 68        // AcT pitch (float4-aligned)
#define SPITCH 65        // scores pitch (scalar access)

// Precomputed bilinear form and bias cross-terms (scaled by 1/1024)
struct Pre {
    float M[HDIM * HDIM];
    float u[HDIM];
    float v[HDIM];
    float s0;
};
__device__ Pre g_pre;

// Split-k partial buffers (each element written by exactly one thread per replay;
// no atomics -> no zeroing pass -> deterministic replays)
__device__ float g_partial[NKC][HDIM * HDIM];
__device__ float g_pu[NKC][HDIM];
__device__ float g_pv[NKC][HDIM];
__device__ float g_ps0[NKC];

// ---------------------------------------------------------------------------
// K1: partial[kc][e][d] = sum_{o in chunk kc} Wp[o][e] * Wc[o][d]
// 32 CTAs (one per k-chunk of 32), 256 threads. Both tiles staged in smem,
// 16x4 register tiles -> FMA-dense, no global loads in the inner loop.
// ---------------------------------------------------------------------------
__global__ void __launch_bounds__(256)
pre_slab(const float* __restrict__ Wp, const float* __restrict__ Wc,
         const float* __restrict__ bp, const float* __restrict__ bc) {
    __shared__ float As[KC][HDIM];   // Wp chunk  (As[k][e])
    __shared__ float Bs[KC][HDIM];   // Wc chunk  (Bs[k][d])
    const int t  = threadIdx.x;
    const int kc = blockIdx.x;
    const int K0 = kc * KC;

    // coalesced float4 staging of both 32x128 tiles
    const float4* Wp4 = (const float4*)(Wp + (size_t)K0 * HDIM);
    const float4* Wc4 = (const float4*)(Wc + (size_t)K0 * HDIM);
    float4* As4 = (float4*)&As[0][0];
    float4* Bs4 = (float4*)&Bs[0][0];
    #pragma unroll
    for (int i = t; i < KC * (HDIM / 4); i += 256) { As4[i] = Wp4[i]; Bs4[i] = Wc4[i]; }
    __syncthreads();

    // warp w -> e rows [16w,16w+16), lane l -> d cols [4l,4l+4)
    const int w = t >> 5, l = t & 31;
    const int e0 = w * 16, d0 = l * 4;
    float acc[16][4];
    #pragma unroll
    for (int i = 0; i < 16; i++)
        #pragma unroll
        for (int j = 0; j < 4; j++) acc[i][j] = 0.f;

    #pragma unroll 4
    for (int k = 0; k < KC; k++) {
        float4 b4 = *(const float4*)&Bs[k][d0];
        #pragma unroll
        for (int i = 0; i < 16; i++) {
            float a = As[k][e0 + i];   // broadcast
            acc[i][0] += a * b4.x;
            acc[i][1] += a * b4.y;
            acc[i][2] += a * b4.z;
            acc[i][3] += a * b4.w;
        }
    }
    #pragma unroll
    for (int i = 0; i < 16; i++)
        *(float4*)&g_partial[kc][(size_t)(e0 + i) * HDIM + d0] =
            make_float4(acc[i][0], acc[i][1], acc[i][2], acc[i][3]);

    // bias partials (zero-valued in this dataset; kept for generality)
    if (t < HDIM) {
        float su = 0.f, sv = 0.f;
        #pragma unroll 4
        for (int k = 0; k < KC; k++) {
            su += As[k][t] * bc[K0 + k];
            sv += Bs[k][t] * bp[K0 + k];
        }
        g_pu[kc][t] = su;
        g_pv[kc][t] = sv;
    }
    if (t == 255) {
        float s = 0.f;
        for (int k = 0; k < KC; k++) s += bp[K0 + k] * bc[K0 + k];
        g_ps0[kc] = s;
    }
}

// ---------------------------------------------------------------------------
// K2: reduce the 32 partials -> g_pre (coalesced, deterministic)
// blocks 0..63 reduce M (256 elems each); block 64 reduces u, v, s0.
// ---------------------------------------------------------------------------
__global__ void __launch_bounds__(256)
pre_reduce() {
    const int t = threadIdx.x, bx = blockIdx.x;
    const float inv = 1.0f / 1024.0f;
    if (bx < 64) {
        int idx = bx * 256 + t;
        float s = 0.f;
        #pragma unroll
        for (int kc = 0; kc < NKC; kc++) s += g_partial[kc][idx];
        g_pre.M[idx] = s * inv;
    } else {
        if (t < HDIM) {
            float s = 0.f;
            #pragma unroll
            for (int kc = 0; kc < NKC; kc++) s += g_pu[kc][t];
            g_pre.u[t] = s * inv;
        } else {
            int e = t - HDIM;
            float s = 0.f;
            #pragma unroll
            for (int kc = 0; kc < NKC; kc++) s += g_pv[kc][e];
            g_pre.v[e] = s * inv;
        }
        if (t == 0) {
            float s = 0.f;
            #pragma unroll
            for (int kc = 0; kc < NKC; kc++) s += g_ps0[kc];
            g_pre.s0 = s * inv;
        }
    }
}

// ---------------------------------------------------------------------------
// Main fused kernel — one CTA per batch element, 512 threads
// ---------------------------------------------------------------------------
struct SmemMain {
    float Ap[LSEQ][HDIM];      // peptide [p][e]       (broadcast reads: pitch 128 ok)
    float Msh[HDIM][HDIM];     // M [e][d]
    float PM[LSEQ][HDIM];      // pep @ M  [p][d]
    float AcT[HDIM][APITCH];   // cdr3 transposed [d][c]
    float S[LSEQ][SPITCH];     // scores -> exp(scores - max)
    float pu[LSEQ], cv[LSEQ], RS[LSEQ], CS[LSEQ];
    float red[16];
    float outP[HDIM], outC[HDIM];
    float mx, Z, s0;
};

__global__ void __launch_bounds__(512, 1)
main_kernel(const float* __restrict__ pep, const float* __restrict__ cdr3,
            float* __restrict__ out) {
    extern __shared__ char smem_raw[];
    SmemMain& sm = *(SmemMain*)smem_raw;
    const int t = threadIdx.x;
    const int b = blockIdx.x;
    const int w = t >> 5, l = t & 31;

    // ---- cooperative loads ----
    const float4* pep4 = (const float4*)(pep + (size_t)b * LSEQ * HDIM);
    const float4* cdr4 = (const float4*)(cdr3 + (size_t)b * LSEQ * HDIM);
    const float4* M4   = (const float4*)g_pre.M;

    float4* Ap4  = (float4*)sm.Ap;    // contiguous pitch-128 copies
    float4* Msh4 = (float4*)sm.Msh;
    for (int i = t; i < LSEQ * (HDIM / 4); i += 512) Ap4[i] = pep4[i];
    for (int i = t; i < HDIM * (HDIM / 4); i += 512) Msh4[i] = M4[i];
    for (int i = t; i < LSEQ * (HDIM / 4); i += 512) {       // cdr3 -> transposed
        int c = i >> 5, d4 = i & 31;
        float4 v = cdr4[i];
        sm.AcT[d4 * 4 + 0][c] = v.x;
        sm.AcT[d4 * 4 + 1][c] = v.y;
        sm.AcT[d4 * 4 + 2][c] = v.z;
        sm.AcT[d4 * 4 + 3][c] = v.w;
    }
    if (t == 0) sm.s0 = g_pre.s0;
    __syncthreads();

    // ---- bias projections (zero in this dataset, kept for generality) ----
    if (t < LSEQ) {
        float s = 0.f;
        for (int e = 0; e < HDIM; e++) s += sm.Ap[t][e] * g_pre.u[e];
        sm.pu[t] = s;
    } else if (t < 2 * LSEQ) {
        int c = t - LSEQ;
        float s = 0.f;
        for (int d = 0; d < HDIM; d++) s += sm.AcT[d][c] * g_pre.v[d];
        sm.cv[c] = s;
    }

    // ---- GEMM1: PM[p][d] = sum_e Ap[p][e] * Msh[e][d] ----
    // 16 warps: warp w -> p in [4w,4w+4), lane l -> d in [4l,4l+4)
    {
        const int p0 = w * 4, d0 = l * 4;
        float acc[4][4];
        #pragma unroll
        for (int i = 0; i < 4; i++)
            #pragma unroll
            for (int j = 0; j < 4; j++) acc[i][j] = 0.f;

        #pragma unroll 4
        for (int e = 0; e < HDIM; e += 4) {
            float4 mv[4];
            #pragma unroll
            for (int q = 0; q < 4; q++) mv[q] = *(const float4*)&sm.Msh[e + q][d0];
            #pragma unroll
            for (int i = 0; i < 4; i++) {
                float4 a = *(const float4*)&sm.Ap[p0 + i][e];   // broadcast
                acc[i][0] += a.x * mv[0].x + a.y * mv[1].x + a.z * mv[2].x + a.w * mv[3].x;
                acc[i][1] += a.x * mv[0].y + a.y * mv[1].y + a.z * mv[2].y + a.w * mv[3].y;
                acc[i][2] += a.x * mv[0].z + a.y * mv[1].z + a.z * mv[2].z + a.w * mv[3].z;
                acc[i][3] += a.x * mv[0].w + a.y * mv[1].w + a.z * mv[2].w + a.w * mv[3].w;
            }
        }
        #pragma unroll
        for (int i = 0; i < 4; i++)
            *(float4*)&sm.PM[p0 + i][d0] =
                make_float4(acc[i][0], acc[i][1], acc[i][2], acc[i][3]);
    }
    __syncthreads();

    // ---- GEMM2: S[p][c] = sum_d PM[p][d]*AcT[d][c] + pu[p] + cv[c] + s0 ----
    // warp w -> p in [4w,4w+4); lane: half = l>>4 covers d-range [64*half,+64),
    // c-tile c0 = (l&15)*4; cross-half reduced via shfl_xor(16).
    {
        const int p0 = w * 4;
        const int db = (l >> 4) * 64;
        const int c0 = (l & 15) * 4;
        float acc[4][4];
        #pragma unroll
        for (int i = 0; i < 4; i++)
            #pragma unroll
            for (int j = 0; j < 4; j++) acc[i][j] = 0.f;

        #pragma unroll 4
        for (int dd = 0; dd < 64; dd += 4) {
            const int d = db + dd;
            float4 av[4];
            #pragma unroll
            for (int q = 0; q < 4; q++) av[q] = *(const float4*)&sm.AcT[d + q][c0];
            #pragma unroll
            for (int i = 0; i < 4; i++) {
                float4 pm = *(const float4*)&sm.PM[p0 + i][d];
                acc[i][0] += pm.x * av[0].x + pm.y * av[1].x + pm.z * av[2].x + pm.w * av[3].x;
                acc[i][1] += pm.x * av[0].y + pm.y * av[1].y + pm.z * av[2].y + pm.w * av[3].y;
                acc[i][2] += pm.x * av[0].z + pm.y * av[1].z + pm.z * av[2].z + pm.w * av[3].z;
                acc[i][3] += pm.x * av[0].w + pm.y * av[1].w + pm.z * av[2].w + pm.w * av[3].w;
            }
        }
        #pragma unroll
        for (int i = 0; i < 4; i++)
            #pragma unroll
            for (int j = 0; j < 4; j++)
                acc[i][j] += __shfl_xor_sync(0xffffffffu, acc[i][j], 16);

        if (l < 16) {
            const float s0v = sm.s0;
            #pragma unroll
            for (int i = 0; i < 4; i++) {
                const float bias = sm.pu[p0 + i] + s0v;
                #pragma unroll
                for (int j = 0; j < 4; j++)
                    sm.S[p0 + i][c0 + j] = acc[i][j] + bias + sm.cv[c0 + j];
            }
        }
    }
    __syncthreads();

    // ---- softmax over all 4096 scores: max ----
    float m = -1e30f;
    #pragma unroll
    for (int q = 0; q < 8; q++) {
        int f = t * 8 + q;
        m = fmaxf(m, sm.S[f >> 6][f & 63]);
    }
    #pragma unroll
    for (int o = 16; o > 0; o >>= 1) m = fmaxf(m, __shfl_xor_sync(~0u, m, o));
    if (l == 0) sm.red[w] = m;
    __syncthreads();
    if (t == 0) {
        float mm = sm.red[0];
        #pragma unroll
        for (int i = 1; i < 16; i++) mm = fmaxf(mm, sm.red[i]);
        sm.mx = mm;
    }
    __syncthreads();

    // ---- exp in place ----
    const float mx = sm.mx;
    #pragma unroll
    for (int q = 0; q < 8; q++) {
        int f = t * 8 + q;
        float* sp = &sm.S[f >> 6][f & 63];
        *sp = __expf(*sp - mx);
    }
    __syncthreads();

    // ---- row sums (RS, weight cdr3) and column sums (CS, weight peptide) ----
    if (t < LSEQ) {
        float s = 0.f;
        for (int c = 0; c < LSEQ; c++) s += sm.S[t][c];
        sm.RS[t] = s;
    } else if (t < 2 * LSEQ) {
        int c = t - LSEQ;
        float s = 0.f;
        for (int p = 0; p < LSEQ; p++) s += sm.S[p][c];
        sm.CS[c] = s;
    }
    __syncthreads();
    if (t < 32) {
        float z = sm.RS[t] + sm.RS[t + 32];
        #pragma unroll
        for (int o = 16; o > 0; o >>= 1) z += __shfl_xor_sync(~0u, z, o);
        if (t == 0) sm.Z = z;
    }
    __syncthreads();

    // ---- epilogue: out[b,h] = (sum_j pep[j][h]*CS[j] + sum_i cdr3[i][h]*RS[i]) / Z
    if (t < HDIM) {
        const int h = t;
        float s = 0.f;
        for (int j = 0; j < LSEQ; j++) s += sm.Ap[j][h] * sm.CS[j];
        sm.outP[h] = s;
    } else if (t < 2 * HDIM) {
        const int h = t - HDIM;
        float s = 0.f;
        for (int i = 0; i < LSEQ; i++) s += sm.AcT[h][i] * sm.RS[i];
        sm.outC[h] = s;
    }
    __syncthreads();
    if (t < HDIM) {
        const float invZ = 1.0f / sm.Z;
        out[(size_t)b * HDIM + t] = (sm.outP[t] + sm.outC[t]) * invZ;
    }
}

// ---------------------------------------------------------------------------
extern "C" void kernel_launch(void* const* d_in, const int* in_sizes, int n_in,
                              void* d_out, int out_size) {
    const float* pep = (const float*)d_in[0];
    const float* cdr = (const float*)d_in[1];
    const float* Wc  = (const float*)d_in[2];
    const float* bc  = (const float*)d_in[3];
    const float* Wp  = (const float*)d_in[4];
    const float* bp  = (const float*)d_in[5];
    float* out = (float*)d_out;

    const int B = in_sizes[0] / (LSEQ * HDIM);   // 256

    cudaFuncSetAttribute(main_kernel, cudaFuncAttributeMaxDynamicSharedMemorySize,
                         (int)sizeof(SmemMain));

    pre_slab<<<NKC, 256>>>(Wp, Wc, bp, bc);
    pre_reduce<<<65, 256>>>();
    main_kernel<<<B, 512, sizeof(SmemMain)>>>(pep, cdr, out);
}

// round 7
// speedup vs baseline: 2.4219x; 2.1411x over previous
#include <cuda_runtime.h>
#include <cuda_bf16.h>
#include <cstdint>

#define LSEQ 64
#define HDIM 128
#define NKC  64          // k-chunks for precompute
#define KC   16          // k per chunk
#define PB   136         // bf16 smem pitch: 272B rows -> ldmatrix conflict-free
#define PF   132         // fp32 smem pitch: float4-aligned, column-friendly
#define SPITCH 65        // scores pitch

// Bias cross terms (fp32) and bf16 bilinear form
struct Pre { float u[HDIM]; float v[HDIM]; float s0; };
__device__ Pre g_pre;
__device__ __nv_bfloat16 g_Mb[HDIM * HDIM];     // M[e][d] bf16, row-major

// Split-k partials (disjoint writes -> no atomics, no zeroing, deterministic)
__device__ float g_partial[NKC][HDIM * HDIM];
__device__ float g_pu[NKC][HDIM];
__device__ float g_pv[NKC][HDIM];
__device__ float g_ps0[NKC];

// ---------------------------------------------------------------------------
// PTX helpers
// ---------------------------------------------------------------------------
__device__ __forceinline__ uint32_t cvta_s(const void* p) {
    return (uint32_t)__cvta_generic_to_shared(p);
}
__device__ __forceinline__ uint32_t pack_bf16x2(float lo, float hi) {
    uint32_t r;
    asm("cvt.rn.bf16x2.f32 %0, %1, %2;" : "=r"(r) : "f"(hi), "f"(lo));
    return r;
}
__device__ __forceinline__ void ldsm_x4(uint32_t* r, uint32_t addr) {
    asm volatile("ldmatrix.sync.aligned.m8n8.x4.shared.b16 {%0,%1,%2,%3}, [%4];\n"
        : "=r"(r[0]), "=r"(r[1]), "=r"(r[2]), "=r"(r[3]) : "r"(addr));
}
__device__ __forceinline__ void ldsm_x4_t(uint32_t* r, uint32_t addr) {
    asm volatile("ldmatrix.sync.aligned.m8n8.x4.trans.shared.b16 {%0,%1,%2,%3}, [%4];\n"
        : "=r"(r[0]), "=r"(r[1]), "=r"(r[2]), "=r"(r[3]) : "r"(addr));
}
__device__ __forceinline__ void mma_bf16(float* c, const uint32_t* a, const uint32_t* b) {
    asm volatile(
        "mma.sync.aligned.m16n8k16.row.col.f32.bf16.bf16.f32 "
        "{%0,%1,%2,%3}, {%4,%5,%6,%7}, {%8,%9}, {%0,%1,%2,%3};\n"
        : "+f"(c[0]), "+f"(c[1]), "+f"(c[2]), "+f"(c[3])
        : "r"(a[0]), "r"(a[1]), "r"(a[2]), "r"(a[3]), "r"(b[0]), "r"(b[1]));
}
// FFMA-only exp (x <= 0 after max subtraction). rel err ~2e-6.
__device__ __forceinline__ float fast_exp(float x) {
    float t = x * 1.4426950408889634f;
    int   ki = __float2int_rn(t);
    float f  = t - (float)ki;
    float p =          0.0013333558f;
    p = fmaf(p, f, 0.0096181291f);
    p = fmaf(p, f, 0.0555041087f);
    p = fmaf(p, f, 0.2402265070f);
    p = fmaf(p, f, 0.6931471806f);
    p = fmaf(p, f, 1.0f);
    ki = ki < -126 ? -126 : ki;
    return p * __int_as_float((127 + ki) << 23);
}

// ---------------------------------------------------------------------------
// K1: partial[kc][e][d] = sum_{o in chunk kc} Wp[o][e] * Wc[o][d]
// 64 CTAs (KC=16 each), 256 threads, smem-staged, 16x4 register tiles.
// ---------------------------------------------------------------------------
__global__ void __launch_bounds__(256)
pre_slab(const float* __restrict__ Wp, const float* __restrict__ Wc,
         const float* __restrict__ bp, const float* __restrict__ bc) {
    __shared__ float As[KC][HDIM];
    __shared__ float Bs[KC][HDIM];
    const int t  = threadIdx.x;
    const int kc = blockIdx.x;
    const int K0 = kc * KC;

    const float4* Wp4 = (const float4*)(Wp + (size_t)K0 * HDIM);
    const float4* Wc4 = (const float4*)(Wc + (size_t)K0 * HDIM);
    float4* As4 = (float4*)&As[0][0];
    float4* Bs4 = (float4*)&Bs[0][0];
    #pragma unroll
    for (int i = t; i < KC * (HDIM / 4); i += 256) { As4[i] = Wp4[i]; Bs4[i] = Wc4[i]; }
    __syncthreads();

    const int w = t >> 5, l = t & 31;
    const int e0 = w * 16, d0 = l * 4;
    float acc[16][4];
    #pragma unroll
    for (int i = 0; i < 16; i++)
        #pragma unroll
        for (int j = 0; j < 4; j++) acc[i][j] = 0.f;

    #pragma unroll
    for (int k = 0; k < KC; k++) {
        float4 b4 = *(const float4*)&Bs[k][d0];
        #pragma unroll
        for (int i = 0; i < 16; i++) {
            float a = As[k][e0 + i];
            acc[i][0] += a * b4.x; acc[i][1] += a * b4.y;
            acc[i][2] += a * b4.z; acc[i][3] += a * b4.w;
        }
    }
    #pragma unroll
    for (int i = 0; i < 16; i++)
        *(float4*)&g_partial[kc][(size_t)(e0 + i) * HDIM + d0] =
            make_float4(acc[i][0], acc[i][1], acc[i][2], acc[i][3]);

    if (t < HDIM) {
        float su = 0.f, sv = 0.f;
        #pragma unroll
        for (int k = 0; k < KC; k++) {
            su += As[k][t] * bc[K0 + k];
            sv += Bs[k][t] * bp[K0 + k];
        }
        g_pu[kc][t] = su;
        g_pv[kc][t] = sv;
    }
    if (t == 255) {
        float s = 0.f;
        for (int k = 0; k < KC; k++) s += bp[K0 + k] * bc[K0 + k];
        g_ps0[kc] = s;
    }
}

// ---------------------------------------------------------------------------
// K2: reduce partials -> bf16 M + fp32 u,v,s0
// ---------------------------------------------------------------------------
__global__ void __launch_bounds__(256)
pre_reduce() {
    const int t = threadIdx.x, bx = blockIdx.x;
    const float inv = 1.0f / 1024.0f;
    if (bx < 64) {
        int idx = bx * 256 + t;
        float s = 0.f;
        #pragma unroll
        for (int kc = 0; kc < NKC; kc++) s += g_partial[kc][idx];
        g_Mb[idx] = __float2bfloat16(s * inv);
    } else {
        if (t < HDIM) {
            float s = 0.f;
            #pragma unroll
            for (int kc = 0; kc < NKC; kc++) s += g_pu[kc][t];
            g_pre.u[t] = s * inv;
        } else {
            int e = t - HDIM;
            float s = 0.f;
            #pragma unroll
            for (int kc = 0; kc < NKC; kc++) s += g_pv[kc][e];
            g_pre.v[e] = s * inv;
        }
        if (t == 0) {
            float s = 0.f;
            #pragma unroll
            for (int kc = 0; kc < NKC; kc++) s += g_ps0[kc];
            g_pre.s0 = s * inv;
        }
    }
}

// ---------------------------------------------------------------------------
// Main fused kernel — one CTA per batch, 512 threads, bf16 tensor-core scores
// ---------------------------------------------------------------------------
struct SmemMain {
    __nv_bfloat16 Apb[LSEQ][PB];   // pep bf16 [p][e]
    __nv_bfloat16 Cb[LSEQ][PB];    // cdr3 bf16 [c][d]  (n x k rows for GEMM2 B)
    __nv_bfloat16 Mb[HDIM][PB];    // M bf16 [e][d]     (k x n rows for GEMM1 B)
    __nv_bfloat16 PMb[LSEQ][PB];   // pep@M bf16 [p][d]
    float Apf[LSEQ][PF];           // pep fp32 (epilogue)
    float Cf[LSEQ][PF];            // cdr3 fp32 (epilogue)
    float S[LSEQ][SPITCH];         // scores -> exp
    float pu[LSEQ], cv[LSEQ], RS[LSEQ], CS[LSEQ];
    float red[16];
    float outP[HDIM], outC[HDIM];
    float mx, Z, s0;
};

__global__ void __launch_bounds__(512, 1)
main_kernel(const float* __restrict__ pep, const float* __restrict__ cdr3,
            float* __restrict__ out) {
    extern __shared__ char smem_raw[];
    SmemMain& sm = *(SmemMain*)smem_raw;
    const int t = threadIdx.x;
    const int b = blockIdx.x;
    const int w = t >> 5, l = t & 31;

    // ---- load + fp32/bf16 dual-write ----
    const float4* pep4 = (const float4*)(pep + (size_t)b * LSEQ * HDIM);
    const float4* cdr4 = (const float4*)(cdr3 + (size_t)b * LSEQ * HDIM);
    for (int i = t; i < LSEQ * (HDIM / 4); i += 512) {
        int r = i >> 5, c4 = (i & 31) * 4;
        float4 v = pep4[i];
        *(float4*)&sm.Apf[r][c4] = v;
        *(uint32_t*)&sm.Apb[r][c4]     = pack_bf16x2(v.x, v.y);
        *(uint32_t*)&sm.Apb[r][c4 + 2] = pack_bf16x2(v.z, v.w);
        float4 u = cdr4[i];
        *(float4*)&sm.Cf[r][c4] = u;
        *(uint32_t*)&sm.Cb[r][c4]      = pack_bf16x2(u.x, u.y);
        *(uint32_t*)&sm.Cb[r][c4 + 2]  = pack_bf16x2(u.z, u.w);
    }
    const uint4* Mb4 = (const uint4*)g_Mb;
    for (int i = t; i < HDIM * (HDIM / 8); i += 512) {   // 8 bf16 per uint4
        int r = i >> 4, c8 = (i & 15) * 8;
        *(uint4*)&sm.Mb[r][c8] = Mb4[i];
    }
    if (t == 0) sm.s0 = g_pre.s0;
    __syncthreads();

    // ---- bias projections (fp32; zero-valued here, kept for generality) ----
    if (t < LSEQ) {
        float s = 0.f;
        for (int e = 0; e < HDIM; e++) s += sm.Apf[t][e] * g_pre.u[e];
        sm.pu[t] = s;
    } else if (t < 2 * LSEQ) {
        int c = t - LSEQ;
        float s = 0.f;
        for (int d = 0; d < HDIM; d++) s += sm.Cf[c][d] * g_pre.v[d];
        sm.cv[c] = s;
    }

    // ---- GEMM1 (tensor cores): PM = Apb @ Mb,  64x128x128 ----
    // warp w: p0=(w&3)*16, n-block nb=(w>>2)*32 (4 n-tiles of 8)
    {
        const int p0 = (w & 3) * 16, nb = (w >> 2) * 32;
        const uint32_t aA  = cvta_s(&sm.Apb[0][0]) + (uint32_t)(p0 + (l & 15)) * (PB * 2) + (l >> 4) * 16;
        const uint32_t aB1 = cvta_s(&sm.Mb[0][0])  + (uint32_t)(l & 15) * (PB * 2) + nb * 2 + (l >> 4) * 16;
        float acc[4][4] = {};
        #pragma unroll
        for (int ks = 0; ks < 8; ks++) {
            uint32_t a[4], b1[4], b2[4];
            ldsm_x4(a, aA + ks * 32);
            ldsm_x4_t(b1, aB1 + ks * (16 * PB * 2));
            ldsm_x4_t(b2, aB1 + ks * (16 * PB * 2) + 32);
            mma_bf16(acc[0], a, b1);
            mma_bf16(acc[1], a, b1 + 2);
            mma_bf16(acc[2], a, b2);
            mma_bf16(acc[3], a, b2 + 2);
        }
        // store PM as bf16 (c-fragment layout)
        const int r0 = p0 + (l >> 2), cc = 2 * (l & 3);
        #pragma unroll
        for (int j = 0; j < 4; j++) {
            int n0 = nb + 8 * j;
            *(uint32_t*)&sm.PMb[r0][n0 + cc]     = pack_bf16x2(acc[j][0], acc[j][1]);
            *(uint32_t*)&sm.PMb[r0 + 8][n0 + cc] = pack_bf16x2(acc[j][2], acc[j][3]);
        }
    }
    __syncthreads();

    // ---- GEMM2 (tensor cores): S = PMb @ Cb^T, 64x64x128, + biases ----
    // warp w: p0=(w&3)*16, c-block cb=(w>>2)*16 (2 n-tiles of 8)
    {
        const int p0 = (w & 3) * 16, cb = (w >> 2) * 16;
        const uint32_t aA = cvta_s(&sm.PMb[0][0]) + (uint32_t)(p0 + (l & 15)) * (PB * 2) + (l >> 4) * 16;
        const uint32_t aB = cvta_s(&sm.Cb[0][0])
                          + (uint32_t)(cb + (l >> 4) * 8 + (l & 7)) * (PB * 2)
                          + ((l >> 3) & 1) * 16;
        float acc[2][4] = {};
        #pragma unroll
        for (int ks = 0; ks < 8; ks++) {
            uint32_t a[4], bb[4];
            ldsm_x4(a, aA + ks * 32);
            ldsm_x4(bb, aB + ks * 32);
            mma_bf16(acc[0], a, bb);
            mma_bf16(acc[1], a, bb + 2);
        }
        const int r0 = p0 + (l >> 2), cc = 2 * (l & 3);
        const float s0v = sm.s0;
        #pragma unroll
        for (int j = 0; j < 2; j++) {
            int c0 = cb + 8 * j + cc;
            sm.S[r0][c0]         = acc[j][0] + sm.pu[r0]     + sm.cv[c0]     + s0v;
            sm.S[r0][c0 + 1]     = acc[j][1] + sm.pu[r0]     + sm.cv[c0 + 1] + s0v;
            sm.S[r0 + 8][c0]     = acc[j][2] + sm.pu[r0 + 8] + sm.cv[c0]     + s0v;
            sm.S[r0 + 8][c0 + 1] = acc[j][3] + sm.pu[r0 + 8] + sm.cv[c0 + 1] + s0v;
        }
    }
    __syncthreads();

    // ---- softmax max ----
    float m = -1e30f;
    #pragma unroll
    for (int q = 0; q < 8; q++) {
        int f = t * 8 + q;
        m = fmaxf(m, sm.S[f >> 6][f & 63]);
    }
    #pragma unroll
    for (int o = 16; o > 0; o >>= 1) m = fmaxf(m, __shfl_xor_sync(~0u, m, o));
    if (l == 0) sm.red[w] = m;
    __syncthreads();
    if (t == 0) {
        float mm = sm.red[0];
        #pragma unroll
        for (int i = 1; i < 16; i++) mm = fmaxf(mm, sm.red[i]);
        sm.mx = mm;
    }
    __syncthreads();

    // ---- exp in place (FFMA-only) ----
    const float mx = sm.mx;
    #pragma unroll
    for (int q = 0; q < 8; q++) {
        int f = t * 8 + q;
        float* sp = &sm.S[f >> 6][f & 63];
        *sp = fast_exp(*sp - mx);
    }
    __syncthreads();

    // ---- row/col sums ----
    if (t < LSEQ) {
        float s = 0.f;
        for (int c = 0; c < LSEQ; c++) s += sm.S[t][c];
        sm.RS[t] = s;
    } else if (t < 2 * LSEQ) {
        int c = t - LSEQ;
        float s = 0.f;
        for (int p = 0; p < LSEQ; p++) s += sm.S[p][c];
        sm.CS[c] = s;
    }
    __syncthreads();
    if (t < 32) {
        float z = sm.RS[t] + sm.RS[t + 32];
        #pragma unroll
        for (int o = 16; o > 0; o >>= 1) z += __shfl_xor_sync(~0u, z, o);
        if (t == 0) sm.Z = z;
    }
    __syncthreads();

    // ---- epilogue (fp32): out[h] = (sum_j pep[j][h]*CS[j] + sum_i cdr3[i][h]*RS[i]) / Z
    if (t < HDIM) {
        float s = 0.f;
        for (int j = 0; j < LSEQ; j++) s += sm.Apf[j][t] * sm.CS[j];
        sm.outP[t] = s;
    } else if (t < 2 * HDIM) {
        const int h = t - HDIM;
        float s = 0.f;
        for (int i = 0; i < LSEQ; i++) s += sm.Cf[i][h] * sm.RS[i];
        sm.outC[h] = s;
    }
    __syncthreads();
    if (t < HDIM) {
        const float invZ = 1.0f / sm.Z;
        out[(size_t)b * HDIM + t] = (sm.outP[t] + sm.outC[t]) * invZ;
    }
}

// ---------------------------------------------------------------------------
extern "C" void kernel_launch(void* const* d_in, const int* in_sizes, int n_in,
                              void* d_out, int out_size) {
    const float* pep = (const float*)d_in[0];
    const float* cdr = (const float*)d_in[1];
    const float* Wc  = (const float*)d_in[2];
    const float* bc  = (const float*)d_in[3];
    const float* Wp  = (const float*)d_in[4];
    const float* bp  = (const float*)d_in[5];
    float* out = (float*)d_out;

    const int B = in_sizes[0] / (LSEQ * HDIM);   // 256

    cudaFuncSetAttribute(main_kernel, cudaFuncAttributeMaxDynamicSharedMemorySize,
                         (int)sizeof(SmemMain));

    pre_slab<<<NKC, 256>>>(Wp, Wc, bp, bc);
    pre_reduce<<<65, 256>>>();
    main_kernel<<<B, 512, sizeof(SmemMain)>>>(pep, cdr, out);
}

// round 8
// speedup vs baseline: 2.6270x; 1.0847x over previous
#include <cuda_runtime.h>
#include <cuda_bf16.h>
#include <cstdint>

#define LSEQ 64
#define HDIM 128
#define NKC  128         // k-chunks for precompute
#define KC   8           // k per chunk
#define PB   136         // bf16 smem pitch: 272B rows -> ldmatrix conflict-free
#define SPITCH 65        // scores pitch

// Bias cross terms (fp32) and bf16 bilinear form
struct Pre { float u[HDIM]; float v[HDIM]; float s0; };
__device__ Pre g_pre;
__device__ __nv_bfloat16 g_Mb[HDIM * HDIM];     // M[e][d] bf16, row-major

// Split-k partials (disjoint writes -> no atomics, no zeroing, deterministic)
__device__ float g_partial[NKC][HDIM * HDIM];
__device__ float g_pu[NKC][HDIM];
__device__ float g_pv[NKC][HDIM];
__device__ float g_ps0[NKC];

// ---------------------------------------------------------------------------
// PTX helpers
// ---------------------------------------------------------------------------
__device__ __forceinline__ uint32_t cvta_s(const void* p) {
    return (uint32_t)__cvta_generic_to_shared(p);
}
__device__ __forceinline__ uint32_t pack_bf16x2(float lo, float hi) {
    uint32_t r;
    asm("cvt.rn.bf16x2.f32 %0, %1, %2;" : "=r"(r) : "f"(hi), "f"(lo));
    return r;
}
__device__ __forceinline__ void ldsm_x4(uint32_t* r, uint32_t addr) {
    asm volatile("ldmatrix.sync.aligned.m8n8.x4.shared.b16 {%0,%1,%2,%3}, [%4];\n"
        : "=r"(r[0]), "=r"(r[1]), "=r"(r[2]), "=r"(r[3]) : "r"(addr));
}
__device__ __forceinline__ void ldsm_x4_t(uint32_t* r, uint32_t addr) {
    asm volatile("ldmatrix.sync.aligned.m8n8.x4.trans.shared.b16 {%0,%1,%2,%3}, [%4];\n"
        : "=r"(r[0]), "=r"(r[1]), "=r"(r[2]), "=r"(r[3]) : "r"(addr));
}
__device__ __forceinline__ void mma_bf16(float* c, const uint32_t* a, const uint32_t* b) {
    asm volatile(
        "mma.sync.aligned.m16n8k16.row.col.f32.bf16.bf16.f32 "
        "{%0,%1,%2,%3}, {%4,%5,%6,%7}, {%8,%9}, {%0,%1,%2,%3};\n"
        : "+f"(c[0]), "+f"(c[1]), "+f"(c[2]), "+f"(c[3])
        : "r"(a[0]), "r"(a[1]), "r"(a[2]), "r"(a[3]), "r"(b[0]), "r"(b[1]));
}
// FFMA-only exp (x <= 0 after max subtraction). rel err ~2e-6.
__device__ __forceinline__ float fast_exp(float x) {
    float t = x * 1.4426950408889634f;
    int   ki = __float2int_rn(t);
    float f  = t - (float)ki;
    float p =          0.0013333558f;
    p = fmaf(p, f, 0.0096181291f);
    p = fmaf(p, f, 0.0555041087f);
    p = fmaf(p, f, 0.2402265070f);
    p = fmaf(p, f, 0.6931471806f);
    p = fmaf(p, f, 1.0f);
    ki = ki < -126 ? -126 : ki;
    return p * __int_as_float((127 + ki) << 23);
}

// ---------------------------------------------------------------------------
// K1: partial[kc][e][d] = sum_{o in chunk kc} Wp[o][e] * Wc[o][d]
// 128 CTAs (KC=8 each), 256 threads, smem-staged, 16x4 register tiles.
// ---------------------------------------------------------------------------
__global__ void __launch_bounds__(256)
pre_slab(const float* __restrict__ Wp, const float* __restrict__ Wc,
         const float* __restrict__ bp, const float* __restrict__ bc) {
    __shared__ float As[KC][HDIM];
    __shared__ float Bs[KC][HDIM];
    const int t  = threadIdx.x;
    const int kc = blockIdx.x;
    const int K0 = kc * KC;

    const float4* Wp4 = (const float4*)(Wp + (size_t)K0 * HDIM);
    const float4* Wc4 = (const float4*)(Wc + (size_t)K0 * HDIM);
    ((float4*)&As[0][0])[t] = Wp4[t];     // KC*(HDIM/4) == 256 exactly
    ((float4*)&Bs[0][0])[t] = Wc4[t];
    __syncthreads();

    const int w = t >> 5, l = t & 31;
    const int e0 = w * 16, d0 = l * 4;
    float acc[16][4];
    #pragma unroll
    for (int i = 0; i < 16; i++)
        #pragma unroll
        for (int j = 0; j < 4; j++) acc[i][j] = 0.f;

    #pragma unroll
    for (int k = 0; k < KC; k++) {
        float4 b4 = *(const float4*)&Bs[k][d0];
        #pragma unroll
        for (int i = 0; i < 16; i++) {
            float a = As[k][e0 + i];
            acc[i][0] += a * b4.x; acc[i][1] += a * b4.y;
            acc[i][2] += a * b4.z; acc[i][3] += a * b4.w;
        }
    }
    #pragma unroll
    for (int i = 0; i < 16; i++)
        *(float4*)&g_partial[kc][(size_t)(e0 + i) * HDIM + d0] =
            make_float4(acc[i][0], acc[i][1], acc[i][2], acc[i][3]);

    if (t < HDIM) {
        float su = 0.f, sv = 0.f;
        #pragma unroll
        for (int k = 0; k < KC; k++) {
            su += As[k][t] * bc[K0 + k];
            sv += Bs[k][t] * bp[K0 + k];
        }
        g_pu[kc][t] = su;
        g_pv[kc][t] = sv;
    }
    if (t == 255) {
        float s = 0.f;
        for (int k = 0; k < KC; k++) s += bp[K0 + k] * bc[K0 + k];
        g_ps0[kc] = s;
    }
}

// ---------------------------------------------------------------------------
// K2: reduce partials -> bf16 M + fp32 u,v,s0 (4 accumulators for MLP)
// ---------------------------------------------------------------------------
__global__ void __launch_bounds__(256)
pre_reduce() {
    const int t = threadIdx.x, bx = blockIdx.x;
    const float inv = 1.0f / 1024.0f;
    if (bx < 64) {
        int idx = bx * 256 + t;
        float a0 = 0.f, a1 = 0.f, a2 = 0.f, a3 = 0.f;
        #pragma unroll
        for (int kc = 0; kc < NKC; kc += 4) {
            a0 += g_partial[kc + 0][idx];
            a1 += g_partial[kc + 1][idx];
            a2 += g_partial[kc + 2][idx];
            a3 += g_partial[kc + 3][idx];
        }
        g_Mb[idx] = __float2bfloat16(((a0 + a1) + (a2 + a3)) * inv);
    } else {
        if (t < HDIM) {
            float s = 0.f;
            #pragma unroll
            for (int kc = 0; kc < NKC; kc++) s += g_pu[kc][t];
            g_pre.u[t] = s * inv;
        } else {
            int e = t - HDIM;
            float s = 0.f;
            #pragma unroll
            for (int kc = 0; kc < NKC; kc++) s += g_pv[kc][e];
            g_pre.v[e] = s * inv;
        }
        if (t == 0) {
            float s = 0.f;
            #pragma unroll
            for (int kc = 0; kc < NKC; kc++) s += g_ps0[kc];
            g_pre.s0 = s * inv;
        }
    }
}

// ---------------------------------------------------------------------------
// Main fused kernel — one CTA per batch, 512 threads, 2 CTAs/SM (one wave)
// ---------------------------------------------------------------------------
struct SmemMain {
    __nv_bfloat16 Apb[LSEQ][PB];       // pep bf16 [p][e]
    __nv_bfloat16 Cb[LSEQ][PB];        // cdr3 bf16 [c][d]
    char MbS[HDIM * PB * 2];           // Mb bf16 [e][d]; S fp32 overlays after GEMM1
    __nv_bfloat16 PMb[LSEQ][PB];       // pep@M bf16 [p][d]
    float EP[16][HDIM];                // epilogue per-warp partials
    float pu[LSEQ], cv[LSEQ], RS[LSEQ], CS[LSEQ];
    float red[16];
    float mx, Z, s0;
};

__global__ void __launch_bounds__(512, 2)
main_kernel(const float* __restrict__ pep, const float* __restrict__ cdr3,
            float* __restrict__ out) {
    extern __shared__ char smem_raw[];
    SmemMain& sm = *(SmemMain*)smem_raw;
    __nv_bfloat16 (*Mb)[PB] = reinterpret_cast<__nv_bfloat16(*)[PB]>(sm.MbS);
    float (*S)[SPITCH]      = reinterpret_cast<float(*)[SPITCH]>(sm.MbS);

    const int t = threadIdx.x;
    const int b = blockIdx.x;
    const int w = t >> 5, l = t & 31;

    // ---- load inputs (bf16 smem copies) + M ----
    const float* pepG = pep  + (size_t)b * LSEQ * HDIM;
    const float* cdrG = cdr3 + (size_t)b * LSEQ * HDIM;
    const float4* pep4 = (const float4*)pepG;
    const float4* cdr4 = (const float4*)cdrG;
    for (int i = t; i < LSEQ * (HDIM / 4); i += 512) {
        int r = i >> 5, c4 = (i & 31) * 4;
        float4 v = pep4[i];
        *(uint32_t*)&sm.Apb[r][c4]     = pack_bf16x2(v.x, v.y);
        *(uint32_t*)&sm.Apb[r][c4 + 2] = pack_bf16x2(v.z, v.w);
        float4 u = cdr4[i];
        *(uint32_t*)&sm.Cb[r][c4]      = pack_bf16x2(u.x, u.y);
        *(uint32_t*)&sm.Cb[r][c4 + 2]  = pack_bf16x2(u.z, u.w);
    }
    const uint4* Mb4 = (const uint4*)g_Mb;
    for (int i = t; i < HDIM * (HDIM / 8); i += 512) {   // 8 bf16 per uint4
        int r = i >> 4, c8 = (i & 15) * 8;
        *(uint4*)&Mb[r][c8] = Mb4[i];
    }
    if (t == 0) sm.s0 = g_pre.s0;
    __syncthreads();

    // ---- bias projections (bf16 reads; zero-valued here, kept for generality)
    if (t < LSEQ) {
        float s = 0.f;
        for (int e = 0; e < HDIM; e++) s += __bfloat162float(sm.Apb[t][e]) * g_pre.u[e];
        sm.pu[t] = s;
    } else if (t < 2 * LSEQ) {
        int c = t - LSEQ;
        float s = 0.f;
        for (int d = 0; d < HDIM; d++) s += __bfloat162float(sm.Cb[c][d]) * g_pre.v[d];
        sm.cv[c] = s;
    }

    // ---- GEMM1 (tensor cores): PM = Apb @ Mb,  64x128x128 ----
    {
        const int p0 = (w & 3) * 16, nb = (w >> 2) * 32;
        const uint32_t aA  = cvta_s(&sm.Apb[0][0]) + (uint32_t)(p0 + (l & 15)) * (PB * 2) + (l >> 4) * 16;
        const uint32_t aB1 = cvta_s(&Mb[0][0])     + (uint32_t)(l & 15) * (PB * 2) + nb * 2 + (l >> 4) * 16;
        float acc[4][4] = {};
        #pragma unroll
        for (int ks = 0; ks < 8; ks++) {
            uint32_t a[4], b1[4], b2[4];
            ldsm_x4(a, aA + ks * 32);
            ldsm_x4_t(b1, aB1 + ks * (16 * PB * 2));
            ldsm_x4_t(b2, aB1 + ks * (16 * PB * 2) + 32);
            mma_bf16(acc[0], a, b1);
            mma_bf16(acc[1], a, b1 + 2);
            mma_bf16(acc[2], a, b2);
            mma_bf16(acc[3], a, b2 + 2);
        }
        const int r0 = p0 + (l >> 2), cc = 2 * (l & 3);
        #pragma unroll
        for (int j = 0; j < 4; j++) {
            int n0 = nb + 8 * j;
            *(uint32_t*)&sm.PMb[r0][n0 + cc]     = pack_bf16x2(acc[j][0], acc[j][1]);
            *(uint32_t*)&sm.PMb[r0 + 8][n0 + cc] = pack_bf16x2(acc[j][2], acc[j][3]);
        }
    }
    __syncthreads();   // Mb dead from here; S takes over its storage

    // ---- GEMM2 (tensor cores): S = PMb @ Cb^T, 64x64x128, + biases ----
    {
        const int p0 = (w & 3) * 16, cb = (w >> 2) * 16;
        const uint32_t aA = cvta_s(&sm.PMb[0][0]) + (uint32_t)(p0 + (l & 15)) * (PB * 2) + (l >> 4) * 16;
        const uint32_t aB = cvta_s(&sm.Cb[0][0])
                          + (uint32_t)(cb + (l >> 4) * 8 + (l & 7)) * (PB * 2)
                          + ((l >> 3) & 1) * 16;
        float acc[2][4] = {};
        #pragma unroll
        for (int ks = 0; ks < 8; ks++) {
            uint32_t a[4], bb[4];
            ldsm_x4(a, aA + ks * 32);
            ldsm_x4(bb, aB + ks * 32);
            mma_bf16(acc[0], a, bb);
            mma_bf16(acc[1], a, bb + 2);
        }
        const int r0 = p0 + (l >> 2), cc = 2 * (l & 3);
        const float s0v = sm.s0;
        #pragma unroll
        for (int j = 0; j < 2; j++) {
            int c0 = cb + 8 * j + cc;
            S[r0][c0]         = acc[j][0] + sm.pu[r0]     + sm.cv[c0]     + s0v;
            S[r0][c0 + 1]     = acc[j][1] + sm.pu[r0]     + sm.cv[c0 + 1] + s0v;
            S[r0 + 8][c0]     = acc[j][2] + sm.pu[r0 + 8] + sm.cv[c0]     + s0v;
            S[r0 + 8][c0 + 1] = acc[j][3] + sm.pu[r0 + 8] + sm.cv[c0 + 1] + s0v;
        }
    }
    __syncthreads();

    // ---- softmax max ----
    float m = -1e30f;
    #pragma unroll
    for (int q = 0; q < 8; q++) {
        int f = t * 8 + q;
        m = fmaxf(m, S[f >> 6][f & 63]);
    }
    #pragma unroll
    for (int o = 16; o > 0; o >>= 1) m = fmaxf(m, __shfl_xor_sync(~0u, m, o));
    if (l == 0) sm.red[w] = m;
    __syncthreads();
    if (t == 0) {
        float mm = sm.red[0];
        #pragma unroll
        for (int i = 1; i < 16; i++) mm = fmaxf(mm, sm.red[i]);
        sm.mx = mm;
    }
    __syncthreads();

    // ---- exp in place (FFMA-only) ----
    const float mx = sm.mx;
    #pragma unroll
    for (int q = 0; q < 8; q++) {
        int f = t * 8 + q;
        float* sp = &S[f >> 6][f & 63];
        *sp = fast_exp(*sp - mx);
    }
    __syncthreads();

    // ---- row/col sums ----
    if (t < LSEQ) {
        float s = 0.f;
        for (int c = 0; c < LSEQ; c++) s += S[t][c];
        sm.RS[t] = s;
    } else if (t < 2 * LSEQ) {
        int c = t - LSEQ;
        float s = 0.f;
        for (int p = 0; p < LSEQ; p++) s += S[p][c];
        sm.CS[c] = s;
    }
    __syncthreads();
    if (t < 32) {
        float z = sm.RS[t] + sm.RS[t + 32];
        #pragma unroll
        for (int o = 16; o > 0; o >>= 1) z += __shfl_xor_sync(~0u, z, o);
        if (t == 0) sm.Z = z;
    }
    __syncthreads();

    // ---- epilogue (fp32, re-read inputs from L2-hot global) ----
    // warp w owns rows 4w..4w+3; lane l owns cols 4l..4l+3 (coalesced float4).
    {
        float a0 = 0.f, a1 = 0.f, a2 = 0.f, a3 = 0.f;
        #pragma unroll
        for (int r = 0; r < 4; r++) {
            const int row = w * 4 + r;
            const float cw = sm.CS[row];
            const float rw = sm.RS[row];
            float4 pv = *(const float4*)&pepG[(size_t)row * HDIM + 4 * l];
            float4 cv4 = *(const float4*)&cdrG[(size_t)row * HDIM + 4 * l];
            a0 += pv.x * cw + cv4.x * rw;
            a1 += pv.y * cw + cv4.y * rw;
            a2 += pv.z * cw + cv4.z * rw;
            a3 += pv.w * cw + cv4.w * rw;
        }
        *(float4*)&sm.EP[w][4 * l] = make_float4(a0, a1, a2, a3);
    }
    __syncthreads();
    if (t < HDIM) {
        float s = 0.f;
        #pragma unroll
        for (int i = 0; i < 16; i++) s += sm.EP[i][t];
        out[(size_t)b * HDIM + t] = s / sm.Z;
    }
}

// ---------------------------------------------------------------------------
extern "C" void kernel_launch(void* const* d_in, const int* in_sizes, int n_in,
                              void* d_out, int out_size) {
    const float* pep = (const float*)d_in[0];
    const float* cdr = (const float*)d_in[1];
    const float* Wc  = (const float*)d_in[2];
    const float* bc  = (const float*)d_in[3];
    const float* Wp  = (const float*)d_in[4];
    const float* bp  = (const float*)d_in[5];
    float* out = (float*)d_out;

    const int B = in_sizes[0] / (LSEQ * HDIM);   // 256

    cudaFuncSetAttribute(main_kernel, cudaFuncAttributeMaxDynamicSharedMemorySize,
                         (int)sizeof(SmemMain));

    pre_slab<<<NKC, 256>>>(Wp, Wc, bp, bc);
    pre_reduce<<<65, 256>>>();
    main_kernel<<<B, 512, sizeof(SmemMain)>>>(pep, cdr, out);
}

// round 9
// speedup vs baseline: 2.6971x; 1.0266x over previous
#include <cuda_runtime.h>
#include <cuda_bf16.h>
#include <cstdint>

#define LSEQ 64
#define HDIM 128
#define NKC  128         // k-chunks for precompute
#define KC   8           // k per chunk
#define PB   136         // bf16 smem pitch: 272B rows -> ldmatrix conflict-free
#define SPITCH 65        // scores pitch

// Bias cross terms (fp32) and bf16 bilinear form
struct Pre { float u[HDIM]; float v[HDIM]; float s0; };
__device__ Pre g_pre;
__device__ __nv_bfloat16 g_Mb[HDIM * HDIM];     // M[e][d] bf16, row-major

// Split-k partials (disjoint writes -> no atomics, no zeroing, deterministic)
__device__ float g_partial[NKC][HDIM * HDIM];
__device__ float g_pu[NKC][HDIM];
__device__ float g_pv[NKC][HDIM];
__device__ float g_ps0[NKC];

// ---------------------------------------------------------------------------
// PTX helpers
// ---------------------------------------------------------------------------
__device__ __forceinline__ uint32_t cvta_s(const void* p) {
    return (uint32_t)__cvta_generic_to_shared(p);
}
__device__ __forceinline__ uint32_t pack_bf16x2(float lo, float hi) {
    uint32_t r;
    asm("cvt.rn.bf16x2.f32 %0, %1, %2;" : "=r"(r) : "f"(hi), "f"(lo));
    return r;
}
__device__ __forceinline__ void ldsm_x4(uint32_t* r, uint32_t addr) {
    asm volatile("ldmatrix.sync.aligned.m8n8.x4.shared.b16 {%0,%1,%2,%3}, [%4];\n"
        : "=r"(r[0]), "=r"(r[1]), "=r"(r[2]), "=r"(r[3]) : "r"(addr));
}
__device__ __forceinline__ void ldsm_x4_t(uint32_t* r, uint32_t addr) {
    asm volatile("ldmatrix.sync.aligned.m8n8.x4.trans.shared.b16 {%0,%1,%2,%3}, [%4];\n"
        : "=r"(r[0]), "=r"(r[1]), "=r"(r[2]), "=r"(r[3]) : "r"(addr));
}
__device__ __forceinline__ void mma_bf16(float* c, const uint32_t* a, const uint32_t* b) {
    asm volatile(
        "mma.sync.aligned.m16n8k16.row.col.f32.bf16.bf16.f32 "
        "{%0,%1,%2,%3}, {%4,%5,%6,%7}, {%8,%9}, {%0,%1,%2,%3};\n"
        : "+f"(c[0]), "+f"(c[1]), "+f"(c[2]), "+f"(c[3])
        : "r"(a[0]), "r"(a[1]), "r"(a[2]), "r"(a[3]), "r"(b[0]), "r"(b[1]));
}
// FFMA-only exp. Valid for the |x| <~ 1 regime of these scores (no max needed:
// scores are O(0.03); the max subtraction cancels exactly in the final ratio).
__device__ __forceinline__ float fast_exp(float x) {
    float t = x * 1.4426950408889634f;
    int   ki = __float2int_rn(t);
    float f  = t - (float)ki;
    float p =          0.0013333558f;
    p = fmaf(p, f, 0.0096181291f);
    p = fmaf(p, f, 0.0555041087f);
    p = fmaf(p, f, 0.2402265070f);
    p = fmaf(p, f, 0.6931471806f);
    p = fmaf(p, f, 1.0f);
    ki = ki < -126 ? -126 : (ki > 126 ? 126 : ki);
    return p * __int_as_float((127 + ki) << 23);
}

// ---------------------------------------------------------------------------
// K1: partial[kc][e][d] = sum_{o in chunk kc} Wp[o][e] * Wc[o][d]
// 128 CTAs (KC=8 each), 512 threads (16 warps -> full FFMA issue), 8x4 tiles.
// ---------------------------------------------------------------------------
__global__ void __launch_bounds__(512)
pre_slab(const float* __restrict__ Wp, const float* __restrict__ Wc,
         const float* __restrict__ bp, const float* __restrict__ bc) {
    __shared__ float As[KC][HDIM];
    __shared__ float Bs[KC][HDIM];
    const int t  = threadIdx.x;
    const int kc = blockIdx.x;
    const int K0 = kc * KC;

    // split staging: threads 0-255 load As, 256-511 load Bs (256 float4 each)
    const float4* Wp4 = (const float4*)(Wp + (size_t)K0 * HDIM);
    const float4* Wc4 = (const float4*)(Wc + (size_t)K0 * HDIM);
    if (t < 256) ((float4*)&As[0][0])[t] = Wp4[t];
    else         ((float4*)&Bs[0][0])[t - 256] = Wc4[t - 256];
    __syncthreads();

    const int w = t >> 5, l = t & 31;
    const int e0 = w * 8, d0 = l * 4;
    float acc[8][4];
    #pragma unroll
    for (int i = 0; i < 8; i++)
        #pragma unroll
        for (int j = 0; j < 4; j++) acc[i][j] = 0.f;

    #pragma unroll
    for (int k = 0; k < KC; k++) {
        float4 b4 = *(const float4*)&Bs[k][d0];
        #pragma unroll
        for (int i = 0; i < 8; i++) {
            float a = As[k][e0 + i];
            acc[i][0] += a * b4.x; acc[i][1] += a * b4.y;
            acc[i][2] += a * b4.z; acc[i][3] += a * b4.w;
        }
    }
    #pragma unroll
    for (int i = 0; i < 8; i++)
        *(float4*)&g_partial[kc][(size_t)(e0 + i) * HDIM + d0] =
            make_float4(acc[i][0], acc[i][1], acc[i][2], acc[i][3]);

    if (t < HDIM) {
        float su = 0.f, sv = 0.f;
        #pragma unroll
        for (int k = 0; k < KC; k++) {
            su += As[k][t] * bc[K0 + k];
            sv += Bs[k][t] * bp[K0 + k];
        }
        g_pu[kc][t] = su;
        g_pv[kc][t] = sv;
    }
    if (t == 511) {
        float s = 0.f;
        for (int k = 0; k < KC; k++) s += bp[K0 + k] * bc[K0 + k];
        g_ps0[kc] = s;
    }
}

// ---------------------------------------------------------------------------
// K2: reduce partials -> bf16 M + fp32 u,v,s0 (4 accumulators for MLP)
// ---------------------------------------------------------------------------
__global__ void __launch_bounds__(256)
pre_reduce() {
    const int t = threadIdx.x, bx = blockIdx.x;
    const float inv = 1.0f / 1024.0f;
    if (bx < 64) {
        int idx = bx * 256 + t;
        float a0 = 0.f, a1 = 0.f, a2 = 0.f, a3 = 0.f;
        #pragma unroll
        for (int kc = 0; kc < NKC; kc += 4) {
            a0 += g_partial[kc + 0][idx];
            a1 += g_partial[kc + 1][idx];
            a2 += g_partial[kc + 2][idx];
            a3 += g_partial[kc + 3][idx];
        }
        g_Mb[idx] = __float2bfloat16(((a0 + a1) + (a2 + a3)) * inv);
    } else {
        if (t < HDIM) {
            float s = 0.f;
            #pragma unroll
            for (int kc = 0; kc < NKC; kc++) s += g_pu[kc][t];
            g_pre.u[t] = s * inv;
        } else {
            int e = t - HDIM;
            float s = 0.f;
            #pragma unroll
            for (int kc = 0; kc < NKC; kc++) s += g_pv[kc][e];
            g_pre.v[e] = s * inv;
        }
        if (t == 0) {
            float s = 0.f;
            #pragma unroll
            for (int kc = 0; kc < NKC; kc++) s += g_ps0[kc];
            g_pre.s0 = s * inv;
        }
    }
}

// ---------------------------------------------------------------------------
// Main fused kernel — one CTA per batch, 512 threads, 2 CTAs/SM (one wave)
// ---------------------------------------------------------------------------
struct SmemMain {
    __nv_bfloat16 Apb[LSEQ][PB];       // pep bf16 [p][e]
    __nv_bfloat16 Cb[LSEQ][PB];        // cdr3 bf16 [c][d]
    char MbS[HDIM * PB * 2];           // Mb bf16 [e][d]; S fp32 overlays after GEMM1
    __nv_bfloat16 PMb[LSEQ][PB];       // pep@M bf16 [p][d]
    float EP[16][HDIM];                // epilogue per-warp partials
    float pu[LSEQ], cv[LSEQ], RS[LSEQ], CS[LSEQ];
    float Z, s0;
};

__global__ void __launch_bounds__(512, 2)
main_kernel(const float* __restrict__ pep, const float* __restrict__ cdr3,
            float* __restrict__ out) {
    extern __shared__ char smem_raw[];
    SmemMain& sm = *(SmemMain*)smem_raw;
    __nv_bfloat16 (*Mb)[PB] = reinterpret_cast<__nv_bfloat16(*)[PB]>(sm.MbS);
    float (*S)[SPITCH]      = reinterpret_cast<float(*)[SPITCH]>(sm.MbS);

    const int t = threadIdx.x;
    const int b = blockIdx.x;
    const int w = t >> 5, l = t & 31;

    // ---- load inputs (bf16 smem copies) + M ----
    const float* pepG = pep  + (size_t)b * LSEQ * HDIM;
    const float* cdrG = cdr3 + (size_t)b * LSEQ * HDIM;
    const float4* pep4 = (const float4*)pepG;
    const float4* cdr4 = (const float4*)cdrG;
    for (int i = t; i < LSEQ * (HDIM / 4); i += 512) {
        int r = i >> 5, c4 = (i & 31) * 4;
        float4 v = pep4[i];
        *(uint32_t*)&sm.Apb[r][c4]     = pack_bf16x2(v.x, v.y);
        *(uint32_t*)&sm.Apb[r][c4 + 2] = pack_bf16x2(v.z, v.w);
        float4 u = cdr4[i];
        *(uint32_t*)&sm.Cb[r][c4]      = pack_bf16x2(u.x, u.y);
        *(uint32_t*)&sm.Cb[r][c4 + 2]  = pack_bf16x2(u.z, u.w);
    }
    const uint4* Mb4 = (const uint4*)g_Mb;
    for (int i = t; i < HDIM * (HDIM / 8); i += 512) {   // 8 bf16 per uint4
        int r = i >> 4, c8 = (i & 15) * 8;
        *(uint4*)&Mb[r][c8] = Mb4[i];
    }
    if (t == 0) sm.s0 = g_pre.s0;
    __syncthreads();

    // ---- bias projections (bf16 reads; zero-valued here, kept for generality)
    if (t < LSEQ) {
        float s = 0.f;
        for (int e = 0; e < HDIM; e++) s += __bfloat162float(sm.Apb[t][e]) * g_pre.u[e];
        sm.pu[t] = s;
    } else if (t < 2 * LSEQ) {
        int c = t - LSEQ;
        float s = 0.f;
        for (int d = 0; d < HDIM; d++) s += __bfloat162float(sm.Cb[c][d]) * g_pre.v[d];
        sm.cv[c] = s;
    }

    // ---- GEMM1 (tensor cores): PM = Apb @ Mb,  64x128x128 ----
    {
        const int p0 = (w & 3) * 16, nb = (w >> 2) * 32;
        const uint32_t aA  = cvta_s(&sm.Apb[0][0]) + (uint32_t)(p0 + (l & 15)) * (PB * 2) + (l >> 4) * 16;
        const uint32_t aB1 = cvta_s(&Mb[0][0])     + (uint32_t)(l & 15) * (PB * 2) + nb * 2 + (l >> 4) * 16;
        float acc[4][4] = {};
        #pragma unroll
        for (int ks = 0; ks < 8; ks++) {
            uint32_t a[4], b1[4], b2[4];
            ldsm_x4(a, aA + ks * 32);
            ldsm_x4_t(b1, aB1 + ks * (16 * PB * 2));
            ldsm_x4_t(b2, aB1 + ks * (16 * PB * 2) + 32);
            mma_bf16(acc[0], a, b1);
            mma_bf16(acc[1], a, b1 + 2);
            mma_bf16(acc[2], a, b2);
            mma_bf16(acc[3], a, b2 + 2);
        }
        const int r0 = p0 + (l >> 2), cc = 2 * (l & 3);
        #pragma unroll
        for (int j = 0; j < 4; j++) {
            int n0 = nb + 8 * j;
            *(uint32_t*)&sm.PMb[r0][n0 + cc]     = pack_bf16x2(acc[j][0], acc[j][1]);
            *(uint32_t*)&sm.PMb[r0 + 8][n0 + cc] = pack_bf16x2(acc[j][2], acc[j][3]);
        }
    }
    __syncthreads();   // Mb dead from here; S takes over its storage

    // ---- GEMM2 (tensor cores): S = exp(PMb @ Cb^T + biases), 64x64x128 ----
    // exp fused into the epilogue; no max pass (scores are O(0.03), and the
    // max subtraction cancels exactly in the final ratio anyway).
    {
        const int p0 = (w & 3) * 16, cb = (w >> 2) * 16;
        const uint32_t aA = cvta_s(&sm.PMb[0][0]) + (uint32_t)(p0 + (l & 15)) * (PB * 2) + (l >> 4) * 16;
        const uint32_t aB = cvta_s(&sm.Cb[0][0])
                          + (uint32_t)(cb + (l >> 4) * 8 + (l & 7)) * (PB * 2)
                          + ((l >> 3) & 1) * 16;
        float acc[2][4] = {};
        #pragma unroll
        for (int ks = 0; ks < 8; ks++) {
            uint32_t a[4], bb[4];
            ldsm_x4(a, aA + ks * 32);
            ldsm_x4(bb, aB + ks * 32);
            mma_bf16(acc[0], a, bb);
            mma_bf16(acc[1], a, bb + 2);
        }
        const int r0 = p0 + (l >> 2), cc = 2 * (l & 3);
        const float s0v = sm.s0;
        const float puA = sm.pu[r0], puB = sm.pu[r0 + 8];
        #pragma unroll
        for (int j = 0; j < 2; j++) {
            int c0 = cb + 8 * j + cc;
            float cv0 = sm.cv[c0], cv1 = sm.cv[c0 + 1];
            S[r0][c0]         = fast_exp(acc[j][0] + puA + cv0 + s0v);
            S[r0][c0 + 1]     = fast_exp(acc[j][1] + puA + cv1 + s0v);
            S[r0 + 8][c0]     = fast_exp(acc[j][2] + puB + cv0 + s0v);
            S[r0 + 8][c0 + 1] = fast_exp(acc[j][3] + puB + cv1 + s0v);
        }
    }
    __syncthreads();

    // ---- row/col sums: 16 warps x 8 tasks, lane-parallel + shfl reduce ----
    #pragma unroll
    for (int q = 0; q < 8; q++) {
        const int task = w + q * 16;      // 0..127
        float s;
        if (task < 64) {                  // row sum (rows conflict-free)
            s = S[task][l] + S[task][l + 32];
        } else {                          // col sum (stride 65 -> conflict-free)
            const int c = task - 64;
            s = S[l][c] + S[l + 32][c];
        }
        #pragma unroll
        for (int o = 16; o > 0; o >>= 1) s += __shfl_xor_sync(~0u, s, o);
        if (l == 0) {
            if (task < 64) sm.RS[task] = s;
            else           sm.CS[task - 64] = s;
        }
    }
    __syncthreads();
    if (t < 32) {
        float z = sm.RS[t] + sm.RS[t + 32];
        #pragma unroll
        for (int o = 16; o > 0; o >>= 1) z += __shfl_xor_sync(~0u, z, o);
        if (t == 0) sm.Z = z;
    }
    __syncthreads();

    // ---- epilogue (fp32, re-read inputs from L2-hot global) ----
    {
        float a0 = 0.f, a1 = 0.f, a2 = 0.f, a3 = 0.f;
        #pragma unroll
        for (int r = 0; r < 4; r++) {
            const int row = w * 4 + r;
            const float cw = sm.CS[row];
            const float rw = sm.RS[row];
            float4 pv = *(const float4*)&pepG[(size_t)row * HDIM + 4 * l];
            float4 cv4 = *(const float4*)&cdrG[(size_t)row * HDIM + 4 * l];
            a0 += pv.x * cw + cv4.x * rw;
            a1 += pv.y * cw + cv4.y * rw;
            a2 += pv.z * cw + cv4.z * rw;
            a3 += pv.w * cw + cv4.w * rw;
        }
        *(float4*)&sm.EP[w][4 * l] = make_float4(a0, a1, a2, a3);
    }
    __syncthreads();
    if (t < HDIM) {
        float s = 0.f;
        #pragma unroll
        for (int i = 0; i < 16; i++) s += sm.EP[i][t];
        out[(size_t)b * HDIM + t] = s / sm.Z;
    }
}

// ---------------------------------------------------------------------------
extern "C" void kernel_launch(void* const* d_in, const int* in_sizes, int n_in,
                              void* d_out, int out_size) {
    const float* pep = (const float*)d_in[0];
    const float* cdr = (const float*)d_in[1];
    const float* Wc  = (const float*)d_in[2];
    const float* bc  = (const float*)d_in[3];
    const float* Wp  = (const float*)d_in[4];
    const float* bp  = (const float*)d_in[5];
    float* out = (float*)d_out;

    const int B = in_sizes[0] / (LSEQ * HDIM);   // 256

    cudaFuncSetAttribute(main_kernel, cudaFuncAttributeMaxDynamicSharedMemorySize,
                         (int)sizeof(SmemMain));

    pre_slab<<<NKC, 512>>>(Wp, Wc, bp, bc);
    pre_reduce<<<65, 256>>>();
    main_kernel<<<B, 512, sizeof(SmemMain)>>>(pep, cdr, out);
}